// round 8
// baseline (speedup 1.0000x reference)
#include <cuda_runtime.h>
#include <cstdint>

// GestureRNN: 2-layer ReLU RNN, B=4096, T=512, IN=10, H=32, NCLS=9.
// R8: HALF-WARP scheme. Lanes 0-15 = batch A, lanes 16-31 = batch B.
// Each lane owns hidden units j=p and j=p+16 (p = lid&15) of its batch.
// h-state stored interleaved in smem (chunk m: 16B of A then 16B of B) so
// every LDS.128 serves BOTH batches -> smem broadcast traffic per batch
// halves (the measured binder). Weights per lane double (2 rows/matrix).
// Recurrence keeps the R4 winning structure: 1 syncwarp/step, parity
// double-buffered h1/h2, register-carried w0 partial, fused chains.

typedef unsigned long long ull;

__device__ __forceinline__ ull ffma2(ull a, ull b, ull c) {
    ull d;
    asm("fma.rn.f32x2 %0, %1, %2, %3;" : "=l"(d) : "l"(a), "l"(b), "l"(c));
    return d;
}
__device__ __forceinline__ float hsum2(ull a) {
    return __uint_as_float((unsigned)a) + __uint_as_float((unsigned)(a >> 32));
}

static constexpr int T_STEPS = 512;
static constexpr int BATCH   = 4096;
static constexpr int IN_DIM  = 10;
static constexpr int NCLS    = 9;
static constexpr int WARPS   = 2;    // 64-thread CTAs, 4 batches per CTA

__global__ void __launch_bounds__(WARPS * 32, 4) rnn_fused_kernel(
    const float* __restrict__ x,
    const float* __restrict__ Wih0, const float* __restrict__ Whh0,
    const float* __restrict__ bih0, const float* __restrict__ bhh0,
    const float* __restrict__ Wih1, const float* __restrict__ Whh1,
    const float* __restrict__ bih1, const float* __restrict__ bhh1,
    const float* __restrict__ Wfc,  const float* __restrict__ bfc,
    float* __restrict__ out)
{
    // Interleaved per-warp state: parity region = 64 floats (256B):
    //   chunk m (m=0..7): bytes [m*32, m*32+16) = batch A h[4m..4m+4)
    //                     bytes [m*32+16, m*32+32) = batch B h[4m..4m+4)
    __shared__ float sH1[WARPS][2][64];
    __shared__ float sH2[WARPS][2][64];

    const int w    = threadIdx.x >> 5;
    const int lid  = threadIdx.x & 31;
    const int half = lid >> 4;          // 0 = batch A, 1 = batch B
    const int p    = lid & 15;
    const int j0   = p;
    const int j1   = p + 16;
    const int b    = (blockIdx.x * WARPS + w) * 2 + half;

    // store offsets in the 64-float parity region
    const int offs0 = (p >> 2) * 8 + (p & 3) + half * 4;  // for j0
    const int offs1 = offs0 + 32;                          // for j1

    // ---- weights: 2 rows per matrix, packed f32x2 over k-pairs ----
    ull wA0[16], wA1[16];   // Whh0 rows j0, j1   (layer-0 recurrence)
    ull wB0[16], wB1[16];   // Wih1 rows          (layer-1 from h1)
    ull wC0[16], wC1[16];   // Whh1 rows          (layer-1 recurrence)
    {
        const ulonglong2* a0 = (const ulonglong2*)(Whh0 + j0 * 32);
        const ulonglong2* a1 = (const ulonglong2*)(Whh0 + j1 * 32);
        const ulonglong2* c0 = (const ulonglong2*)(Wih1 + j0 * 32);
        const ulonglong2* c1 = (const ulonglong2*)(Wih1 + j1 * 32);
        const ulonglong2* d0 = (const ulonglong2*)(Whh1 + j0 * 32);
        const ulonglong2* d1 = (const ulonglong2*)(Whh1 + j1 * 32);
#pragma unroll
        for (int m = 0; m < 8; m++) {
            ulonglong2 t;
            t = a0[m]; wA0[2*m] = t.x; wA0[2*m+1] = t.y;
            t = a1[m]; wA1[2*m] = t.x; wA1[2*m+1] = t.y;
            t = c0[m]; wB0[2*m] = t.x; wB0[2*m+1] = t.y;
            t = c1[m]; wB1[2*m] = t.x; wB1[2*m+1] = t.y;
            t = d0[m]; wC0[2*m] = t.x; wC0[2*m+1] = t.y;
            t = d1[m]; wC1[2*m] = t.x; wC1[2*m+1] = t.y;
        }
    }
    // input-projection weights (rows are 40B, 8-byte aligned -> direct ull)
    ull wx0[5], wx1[5];
    {
        const ull* q0 = (const ull*)(Wih0 + j0 * IN_DIM);
        const ull* q1 = (const ull*)(Wih0 + j1 * IN_DIM);
#pragma unroll
        for (int m = 0; m < 5; m++) { wx0[m] = q0[m]; wx1[m] = q1[m]; }
    }
    const float b0j0 = bih0[j0] + bhh0[j0];
    const float b0j1 = bih0[j1] + bhh0[j1];
    const float b1j0 = bih1[j0] + bhh1[j0];
    const float b1j1 = bih1[j1] + bhh1[j1];

    const float* xb = x + (size_t)b * (T_STEPS * IN_DIM);

    // ---- prologue: h1_0 = relu(xp_0); h2_{-1} = 0; publish to parity 0 ----
    ull xr[5];
    {
        const ull* xq = (const ull*)xb;
#pragma unroll
        for (int m = 0; m < 5; m++) xr[m] = xq[m];
        ull a0 = 0ull, a1 = 0ull;
#pragma unroll
        for (int m = 0; m < 5; m++) {
            a0 = ffma2(wx0[m], xr[m], a0);
            a1 = ffma2(wx1[m], xr[m], a1);
        }
        sH1[w][0][offs0] = fmaxf(b0j0 + hsum2(a0), 0.f);
        sH1[w][0][offs1] = fmaxf(b0j1 + hsum2(a1), 0.f);
        sH2[w][0][offs0] = 0.f;
        sH2[w][0][offs1] = 0.f;
        // prefetch x_1
        const ull* xn = (const ull*)(xb + IN_DIM);
#pragma unroll
        for (int m = 0; m < 5; m++) xr[m] = xn[m];
    }
    __syncwarp();

    // ---- main loop: block t reads parity t&1, writes (t&1)^1 ----
    for (int t = 0; t < T_STEPS; t++) {
        const int P = t & 1;
        const int Q = P ^ 1;
        const ulonglong2* r1 = (const ulonglong2*)sH1[w][P] + half;
        const ulonglong2* r2 = (const ulonglong2*)sH2[w][P] + half;

        ull h2a0 = 0ull, h2a1 = 0ull;   // wi1·h1_t + wh1·h2_{t-1}
        ull ca0  = 0ull, ca1  = 0ull;   // w0·h1_t  (-> h1_{t+1})
#pragma unroll
        for (int m = 0; m < 8; m++) {
            ulonglong2 q = r1[2*m];     // h1_t chunk m (this batch)
            ulonglong2 r = r2[2*m];     // h2_{t-1} chunk m
            h2a0 = ffma2(wB0[2*m],   q.x, h2a0);
            h2a1 = ffma2(wB1[2*m],   q.x, h2a1);
            ca0  = ffma2(wA0[2*m],   q.x, ca0);
            ca1  = ffma2(wA1[2*m],   q.x, ca1);
            h2a0 = ffma2(wC0[2*m],   r.x, h2a0);
            h2a1 = ffma2(wC1[2*m],   r.x, h2a1);
            h2a0 = ffma2(wB0[2*m+1], q.y, h2a0);
            h2a1 = ffma2(wB1[2*m+1], q.y, h2a1);
            ca0  = ffma2(wA0[2*m+1], q.y, ca0);
            ca1  = ffma2(wA1[2*m+1], q.y, ca1);
            h2a0 = ffma2(wC0[2*m+1], r.y, h2a0);
            h2a1 = ffma2(wC1[2*m+1], r.y, h2a1);
        }
        const float h2v0 = fmaxf(b1j0 + hsum2(h2a0), 0.f);
        const float h2v1 = fmaxf(b1j1 + hsum2(h2a1), 0.f);

        // xp_{t+1} from prefetched xr
        ull a0 = 0ull, a1 = 0ull;
#pragma unroll
        for (int m = 0; m < 5; m++) {
            a0 = ffma2(wx0[m], xr[m], a0);
            a1 = ffma2(wx1[m], xr[m], a1);
        }
        const float h1v0 = fmaxf(b0j0 + hsum2(a0) + hsum2(ca0), 0.f);
        const float h1v1 = fmaxf(b0j1 + hsum2(a1) + hsum2(ca1), 0.f);

        // prefetch x_{t+2} (clamped; t=511 value unused)
        {
            const int tn = (t + 2 < T_STEPS) ? (t + 2) : (T_STEPS - 1);
            const ull* xn = (const ull*)(xb + tn * IN_DIM);
#pragma unroll
            for (int m = 0; m < 5; m++) xr[m] = xn[m];
        }

        // publish h1_{t+1}, h2_t to parity Q
        sH1[w][Q][offs0] = h1v0;
        sH1[w][Q][offs1] = h1v1;
        sH2[w][Q][offs0] = h2v0;
        sH2[w][Q][offs1] = h2v1;
        __syncwarp();
    }

    // h2_511 was written by block t=511 to parity (511&1)^1 = 0
    if (p < NCLS) {
        float o = bfc[p];
        const float* wr = Wfc + p * 32;
        const float* h2f = sH2[w][0];
#pragma unroll
        for (int j = 0; j < 32; j++)
            o += h2f[(j >> 2) * 8 + (j & 3) + half * 4] * wr[j];
        out[(size_t)b * NCLS + p] = o;
    }
}

extern "C" void kernel_launch(void* const* d_in, const int* in_sizes, int n_in,
                              void* d_out, int out_size)
{
    const float* x    = (const float*)d_in[0];
    const float* Wih0 = (const float*)d_in[1];
    const float* Whh0 = (const float*)d_in[2];
    const float* bih0 = (const float*)d_in[3];
    const float* bhh0 = (const float*)d_in[4];
    const float* Wih1 = (const float*)d_in[5];
    const float* Whh1 = (const float*)d_in[6];
    const float* bih1 = (const float*)d_in[7];
    const float* bhh1 = (const float*)d_in[8];
    const float* Wfc  = (const float*)d_in[9];
    const float* bfc  = (const float*)d_in[10];
    float* out = (float*)d_out;

    rnn_fused_kernel<<<BATCH / (WARPS * 2), WARPS * 32>>>(
        x, Wih0, Whh0, bih0, bhh0, Wih1, Whh1, bih1, bhh1, Wfc, bfc, out);
}